// round 15
// baseline (speedup 1.0000x reference)
#include <cuda_runtime.h>
#include <cuda_fp16.h>
#include <cstdint>

// ScaledDotProductAttention B=4,H=12,S=2048,D=32 fp32, mask int32 [B,1,S,S]
// fp16 m16n8k16 mma.sync flash attention, no-max softmax, f16x2 ex2.
// R15 = R14 resubmit (infra failure): software-pipelined PV — iteration kb
// runs PV(kb-1) with the previous iteration's pfrag (no same-iter
// dependency), then QK(kb)+softmax(kb). Merged mask-pack + K/Vt-prep
// prologue. 2 smem buffers, cp.async.

#define S_LEN   2048
#define HEADS   12
#define BLOCK_M 128
#define BLOCK_N 128
#define N_KTILES (S_LEN / BLOCK_N)      // 16
#define MWORDS  (S_LEN / 32)            // 64
#define QSCALE  ((float)(0.17677669529663687 * 1.4426950408889634))

#define K_STRIDE  20                    // uints per K row (LDSM conflict-free)
#define VT_STRIDE 68                    // uints per Vt row (conflict-free)
#define K_ROW_B   (K_STRIDE * 4)        // 80
#define VT_ROW_B  (VT_STRIDE * 4)       // 272
#define VT_OFF    (BLOCK_N * K_ROW_B)           // 10240
#define TILE_BYTES (VT_OFF + 32 * VT_ROW_B)     // 18944
#define CHUNKS    (TILE_BYTES / 16)             // 1184
#define ONE_H2  0x3C003C00u

#define MASK_BLOCKS 4096
#define PREP_BLOCKS (N_KTILES * 48)     // 768

__device__ uint32_t g_packed_mask[(size_t)4 * S_LEN * MWORDS];
__device__ __align__(16) char g_kvt[(size_t)48 * N_KTILES * TILE_BYTES];

__device__ __forceinline__ uint32_t packh2(float lo, float hi) {
    half2 h = __floats2half2_rn(lo, hi);
    return *reinterpret_cast<uint32_t*>(&h);
}

// Merged prologue: blocks [0,4096) pack mask bits (4 int4/thread);
// blocks [4096,4864) build fp16 K/Vt tiles in padded smem layout.
__global__ void prep_all_kernel(const int4* __restrict__ mask,
                                const float* __restrict__ K,
                                const float* __restrict__ V) {
    const int tid = threadIdx.x;
    if (blockIdx.x < MASK_BLOCKS) {
        const size_t i0 = (size_t)blockIdx.x * 1024 + tid;
        int4 v0 = mask[i0];
        int4 v1 = mask[i0 + 256];
        int4 v2 = mask[i0 + 512];
        int4 v3 = mask[i0 + 768];
        const unsigned lane = tid & 31;
        const int sh4 = 4 * (lane & 7);
        #pragma unroll
        for (int it = 0; it < 4; it++) {
            int4 v = (it == 0) ? v0 : (it == 1) ? v1 : (it == 2) ? v2 : v3;
            uint32_t nib = (v.x ? 1u : 0u) | (v.y ? 2u : 0u) |
                           (v.z ? 4u : 0u) | (v.w ? 8u : 0u);
            uint32_t word = nib << sh4;
            word |= __shfl_xor_sync(0xffffffffu, word, 1);
            word |= __shfl_xor_sync(0xffffffffu, word, 2);
            word |= __shfl_xor_sync(0xffffffffu, word, 4);
            if ((lane & 7) == 0)
                g_packed_mask[(i0 + it * 256) >> 3] = word;
        }
    } else {
        const int pb = blockIdx.x - MASK_BLOCKS;
        const int tile = pb & (N_KTILES - 1);
        const int bh = pb >> 4;
        const size_t base = (size_t)bh * S_LEN * 32 + (size_t)tile * BLOCK_N * 32;
        char* dstk = g_kvt + ((size_t)bh * N_KTILES + tile) * TILE_BYTES;
        char* dstv = dstk + VT_OFF;
        #pragma unroll
        for (int it = 0; it < 4; it++) {
            const int i = tid + it * 256;
            const int r = i >> 3, c4 = i & 7;
            float4 kv = *reinterpret_cast<const float4*>(K + base + (size_t)r * 32 + c4 * 4);
            *reinterpret_cast<uint2*>(dstk + r * K_ROW_B + c4 * 8) =
                make_uint2(packh2(kv.x, kv.y), packh2(kv.z, kv.w));
        }
        const int warp = tid >> 5, lane = tid & 31, g = lane >> 2, t = lane & 3;
        const int row = (warp & 3) * 8 + g;
        const int jb  = (warp >> 2) * 32;
        #pragma unroll
        for (int it = 0; it < 8; it++) {
            const int j = jb + it * 4 + t;
            const float* vp = V + base + (size_t)(2 * j) * 32 + row;
            *reinterpret_cast<uint32_t*>(dstv + row * VT_ROW_B + j * 4) =
                packh2(vp[0], vp[32]);
        }
    }
}

__device__ __forceinline__ uint32_t h2ex2(uint32_t x) {
    uint32_t r; asm("ex2.approx.f16x2 %0, %1;" : "=r"(r) : "r"(x)); return r;
}
__device__ __forceinline__ uint32_t smem_u32(const void* p) {
    uint32_t a;
    asm("{ .reg .u64 t; cvta.to.shared.u64 t, %1; cvt.u32.u64 %0, t; }" : "=r"(a) : "l"(p));
    return a;
}
__device__ __forceinline__ void cpasync16(uint32_t dst, const void* src) {
    asm volatile("cp.async.cg.shared.global [%0], [%1], 16;" :: "r"(dst), "l"(src));
}
#define CP_COMMIT() asm volatile("cp.async.commit_group;" ::: "memory")
#define CP_WAIT1()  asm volatile("cp.async.wait_group 1;" ::: "memory")

__device__ __forceinline__ void ldsm_x4(uint32_t& r0, uint32_t& r1, uint32_t& r2,
                                        uint32_t& r3, uint32_t addr) {
    asm volatile("ldmatrix.sync.aligned.m8n8.x4.shared.b16 {%0,%1,%2,%3}, [%4];"
                 : "=r"(r0), "=r"(r1), "=r"(r2), "=r"(r3) : "r"(addr));
}
__device__ __forceinline__ void mma16816(float c[4], const uint32_t a[4],
                                         uint32_t b0, uint32_t b1) {
    asm volatile(
        "mma.sync.aligned.m16n8k16.row.col.f32.f16.f16.f32 "
        "{%0,%1,%2,%3}, {%4,%5,%6,%7}, {%8,%9}, {%0,%1,%2,%3};\n"
        : "+f"(c[0]), "+f"(c[1]), "+f"(c[2]), "+f"(c[3])
        : "r"(a[0]), "r"(a[1]), "r"(a[2]), "r"(a[3]), "r"(b0), "r"(b1));
}

__global__ void __launch_bounds__(256, 2)
sdpa_fp16_kernel(const float* __restrict__ Q, float* __restrict__ O) {
    __shared__ __align__(16) char sbuf[2][TILE_BYTES];

    const int tid  = threadIdx.x;
    const int warp = tid >> 5;          // 0..7
    const int lane = tid & 31;
    const int g    = lane >> 2;
    const int t    = lane & 3;

    const int bh = blockIdx.y, b = bh / HEADS;
    const size_t base = (size_t)bh * S_LEN * 32;
    const int q_tile = blockIdx.x * BLOCK_M;
    const int q0 = q_tile + warp * 16 + g;           // rows q0, q0+8
    const uint32_t* mp0 = g_packed_mask + (size_t)b * S_LEN * MWORDS + (size_t)q0 * MWORDS;
    const uint32_t* mp1 = mp0 + 8 * MWORDS;

    const int lrow = lane & 7, lmat = lane >> 3;
    const uint32_t k_lane_off = (uint32_t)(lrow * K_ROW_B + 16 * lmat);
    const uint32_t v_lane_off = (uint32_t)(VT_OFF + lrow * VT_ROW_B + 16 * lmat);
    const uint32_t sb0 = smem_u32(&sbuf[0][0]);
    const uint32_t sb1 = smem_u32(&sbuf[1][0]);

    const uint32_t cpd0 = sb0 + tid * 16;
    const uint32_t cpd1 = sb1 + tid * 16;
    const char* cps = g_kvt + (size_t)bh * N_KTILES * TILE_BYTES + tid * 16;
    const bool cp5 = tid < (CHUNKS - 1024);

    // ---- Q A-fragments (fp16, pre-scaled into log2 domain) ----
    uint32_t qa[2][4];
    #pragma unroll
    for (int kt = 0; kt < 2; kt++) {
        const int c0 = kt * 16 + 2 * t;
        float2 a0 = *reinterpret_cast<const float2*>(Q + base + (size_t)q0 * 32 + c0);
        float2 a1 = *reinterpret_cast<const float2*>(Q + base + (size_t)(q0 + 8) * 32 + c0);
        float2 a2 = *reinterpret_cast<const float2*>(Q + base + (size_t)q0 * 32 + c0 + 8);
        float2 a3 = *reinterpret_cast<const float2*>(Q + base + (size_t)(q0 + 8) * 32 + c0 + 8);
        qa[kt][0] = packh2(QSCALE * a0.x, QSCALE * a0.y);
        qa[kt][1] = packh2(QSCALE * a1.x, QSCALE * a1.y);
        qa[kt][2] = packh2(QSCALE * a2.x, QSCALE * a2.y);
        qa[kt][3] = packh2(QSCALE * a3.x, QSCALE * a3.y);
    }

    float o[4][4];
    #pragma unroll
    for (int i = 0; i < 4; i++)
        #pragma unroll
        for (int j = 0; j < 4; j++) o[i][j] = 0.f;
    float osum[4] = {0.f, 0.f, 0.f, 0.f};
    uint32_t pfrag[16][2];

    auto fill_tile = [&](int tile, uint32_t cpd) {
        const char* src = cps + (size_t)tile * TILE_BYTES;
        #pragma unroll
        for (int it = 0; it < 4; it++) cpasync16(cpd + it * 4096, src + it * 4096);
        if (cp5) cpasync16(cpd + 4 * 4096, src + 4 * 4096);
    };

    auto qk_softmax = [&](int kb, uint32_t sbc) {
        const uint32_t kbase = sbc + k_lane_off;
        uint4 mwa = *reinterpret_cast<const uint4*>(mp0 + kb * 4);
        uint4 mwb = *reinterpret_cast<const uint4*>(mp1 + kb * 4);
        const uint32_t w0[4] = {mwa.x, mwa.y, mwa.z, mwa.w};
        const uint32_t w1[4] = {mwb.x, mwb.y, mwb.z, mwb.w};
        #pragma unroll
        for (int h = 0; h < 2; h++) {
            float s[8][4];
            #pragma unroll
            for (int nt = 0; nt < 8; nt++)
                #pragma unroll
                for (int j = 0; j < 4; j++) s[nt][j] = 0.f;
            const uint32_t kh = kbase + h * (64 * K_ROW_B);
            #pragma unroll
            for (int nt = 0; nt < 8; nt++) {
                uint32_t b0, b1, b2, b3;
                ldsm_x4(b0, b1, b2, b3, kh + nt * (8 * K_ROW_B));
                mma16816(s[nt], qa[0], b0, b1);
                mma16816(s[nt], qa[1], b2, b3);
            }
            #pragma unroll
            for (int nt = 0; nt < 8; nt++) {
                const int wi = 2 * h + (nt >> 2);
                const int sh = (nt & 3) * 8 + 2 * t;
                uint32_t b0 = w0[wi] >> sh;
                uint32_t b1 = w1[wi] >> sh;
                float s0 = (b0 & 1u) ? -1e9f : s[nt][0];
                float s1 = (b0 & 2u) ? -1e9f : s[nt][1];
                float s2 = (b1 & 1u) ? -1e9f : s[nt][2];
                float s3 = (b1 & 2u) ? -1e9f : s[nt][3];
                pfrag[8 * h + nt][0] = h2ex2(packh2(s0, s1));
                pfrag[8 * h + nt][1] = h2ex2(packh2(s2, s3));
            }
        }
    };

    auto do_pv = [&](uint32_t sbc) {
        const uint32_t vbase = sbc + v_lane_off;
        #pragma unroll
        for (int nt2 = 0; nt2 < 4; nt2++) {
            uint32_t vb[16];
            const uint32_t va = vbase + nt2 * (8 * VT_ROW_B);
            #pragma unroll
            for (int c = 0; c < 4; c++)
                ldsm_x4(vb[4 * c], vb[4 * c + 1], vb[4 * c + 2], vb[4 * c + 3],
                        va + 64 * c);
            #pragma unroll
            for (int kt = 0; kt < 8; kt++) {
                uint32_t pa[4] = {pfrag[2 * kt][0], pfrag[2 * kt][1],
                                  pfrag[2 * kt + 1][0], pfrag[2 * kt + 1][1]};
                mma16816(o[nt2], pa, vb[2 * kt], vb[2 * kt + 1]);
            }
        }
        #pragma unroll
        for (int kt = 0; kt < 8; kt++) {
            uint32_t pa[4] = {pfrag[2 * kt][0], pfrag[2 * kt][1],
                              pfrag[2 * kt + 1][0], pfrag[2 * kt + 1][1]};
            mma16816(osum, pa, ONE_H2, ONE_H2);
        }
    };

    // ---- prologue: fill tiles 0 and 1 ----
    fill_tile(0, cpd0);
    CP_COMMIT();
    fill_tile(1, cpd1);
    CP_COMMIT();
    CP_WAIT1();          // tile 0 complete (tile 1 in flight)
    __syncthreads();
    qk_softmax(0, sb0);  // pfrag = softmax(tile 0)

    for (int kb = 1; kb < N_KTILES; kb++) {
        const uint32_t sbPrev = (kb & 1) ? sb0 : sb1;   // tile kb-1
        const uint32_t sbCur  = (kb & 1) ? sb1 : sb0;   // tile kb
        const uint32_t cpdPrev = (kb & 1) ? cpd0 : cpd1;

        do_pv(sbPrev);               // PV(kb-1): inputs ready, no stall
        __syncthreads();             // Vt(kb-1) reads done -> buffer free
        if (kb + 1 < N_KTILES) fill_tile(kb + 1, cpdPrev);
        CP_COMMIT();
        CP_WAIT1();                  // fill(kb) complete
        __syncthreads();
        qk_softmax(kb, sbCur);       // results consumed next iteration
    }
    do_pv(sb1);                      // PV(tile 15)

    // ---- epilogue ----
    const float inv0 = 1.f / osum[0];   // row q0
    const float inv1 = 1.f / osum[2];   // row q0+8
    #pragma unroll
    for (int nt2 = 0; nt2 < 4; nt2++) {
        const int c = nt2 * 8 + 2 * t;
        float2 va = make_float2(o[nt2][0] * inv0, o[nt2][1] * inv0);
        float2 vb = make_float2(o[nt2][2] * inv1, o[nt2][3] * inv1);
        *reinterpret_cast<float2*>(O + base + (size_t)q0 * 32 + c) = va;
        *reinterpret_cast<float2*>(O + base + (size_t)(q0 + 8) * 32 + c) = vb;
    }
}

extern "C" void kernel_launch(void* const* d_in, const int* in_sizes, int n_in,
                              void* d_out, int out_size) {
    const float* Q = (const float*)d_in[0];
    const float* K = (const float*)d_in[1];
    const float* V = (const float*)d_in[2];
    const int4* mask = (const int4*)d_in[3];
    float* O = (float*)d_out;

    prep_all_kernel<<<MASK_BLOCKS + PREP_BLOCKS, 256>>>(mask, K, V);
    dim3 grid(S_LEN / BLOCK_M, 48);   // (16, 48)
    sdpa_fp16_kernel<<<grid, 256>>>(Q, O);
}

// round 16
// speedup vs baseline: 1.3274x; 1.3274x over previous
#include <cuda_runtime.h>
#include <cuda_fp16.h>
#include <cstdint>

// ScaledDotProductAttention B=4,H=12,S=2048,D=32 fp32, mask int32 [B,1,S,S]
// fp16 m16n8k16 mma.sync flash attention, no-max softmax, f16x2 ex2.
// R16: R13 loop (best) with BLOCK_M=64 / 128-thread CTAs -> 4 CTAs/SM =
// 4 independent barrier domains for cross-CTA phase overlap (per-warp work
// invariant). Merged mask-pack + K/Vt-prep prologue, cp.async fills, LDSM.

#define S_LEN   2048
#define HEADS   12
#define BLOCK_M 64
#define BLOCK_N 128
#define N_KTILES (S_LEN / BLOCK_N)      // 16
#define MWORDS  (S_LEN / 32)            // 64
#define QSCALE  ((float)(0.17677669529663687 * 1.4426950408889634))

#define K_STRIDE  20                    // uints per K row (LDSM conflict-free)
#define VT_STRIDE 68                    // uints per Vt row (conflict-free)
#define K_ROW_B   (K_STRIDE * 4)        // 80
#define VT_ROW_B  (VT_STRIDE * 4)       // 272
#define VT_OFF    (BLOCK_N * K_ROW_B)           // 10240
#define TILE_BYTES (VT_OFF + 32 * VT_ROW_B)     // 18944
#define CHUNKS    (TILE_BYTES / 16)             // 1184
#define ONE_H2  0x3C003C00u

#define MASK_BLOCKS 4096
#define PREP_BLOCKS (N_KTILES * 48)     // 768

__device__ uint32_t g_packed_mask[(size_t)4 * S_LEN * MWORDS];
__device__ __align__(16) char g_kvt[(size_t)48 * N_KTILES * TILE_BYTES];

__device__ __forceinline__ uint32_t packh2(float lo, float hi) {
    half2 h = __floats2half2_rn(lo, hi);
    return *reinterpret_cast<uint32_t*>(&h);
}

// Merged prologue: blocks [0,4096) pack mask bits (4 int4/thread);
// blocks [4096,4864) build fp16 K/Vt tiles in padded smem layout.
__global__ void prep_all_kernel(const int4* __restrict__ mask,
                                const float* __restrict__ K,
                                const float* __restrict__ V) {
    const int tid = threadIdx.x;
    if (blockIdx.x < MASK_BLOCKS) {
        const size_t i0 = (size_t)blockIdx.x * 1024 + tid;
        int4 v0 = mask[i0];
        int4 v1 = mask[i0 + 256];
        int4 v2 = mask[i0 + 512];
        int4 v3 = mask[i0 + 768];
        const unsigned lane = tid & 31;
        const int sh4 = 4 * (lane & 7);
        #pragma unroll
        for (int it = 0; it < 4; it++) {
            int4 v = (it == 0) ? v0 : (it == 1) ? v1 : (it == 2) ? v2 : v3;
            uint32_t nib = (v.x ? 1u : 0u) | (v.y ? 2u : 0u) |
                           (v.z ? 4u : 0u) | (v.w ? 8u : 0u);
            uint32_t word = nib << sh4;
            word |= __shfl_xor_sync(0xffffffffu, word, 1);
            word |= __shfl_xor_sync(0xffffffffu, word, 2);
            word |= __shfl_xor_sync(0xffffffffu, word, 4);
            if ((lane & 7) == 0)
                g_packed_mask[(i0 + it * 256) >> 3] = word;
        }
    } else {
        const int pb = blockIdx.x - MASK_BLOCKS;
        const int tile = pb & (N_KTILES - 1);
        const int bh = pb >> 4;
        const size_t base = (size_t)bh * S_LEN * 32 + (size_t)tile * BLOCK_N * 32;
        char* dstk = g_kvt + ((size_t)bh * N_KTILES + tile) * TILE_BYTES;
        char* dstv = dstk + VT_OFF;
        #pragma unroll
        for (int it = 0; it < 4; it++) {
            const int i = tid + it * 256;
            const int r = i >> 3, c4 = i & 7;
            float4 kv = *reinterpret_cast<const float4*>(K + base + (size_t)r * 32 + c4 * 4);
            *reinterpret_cast<uint2*>(dstk + r * K_ROW_B + c4 * 8) =
                make_uint2(packh2(kv.x, kv.y), packh2(kv.z, kv.w));
        }
        const int warp = tid >> 5, lane = tid & 31, g = lane >> 2, t = lane & 3;
        const int row = (warp & 3) * 8 + g;
        const int jb  = (warp >> 2) * 32;
        #pragma unroll
        for (int it = 0; it < 8; it++) {
            const int j = jb + it * 4 + t;
            const float* vp = V + base + (size_t)(2 * j) * 32 + row;
            *reinterpret_cast<uint32_t*>(dstv + row * VT_ROW_B + j * 4) =
                packh2(vp[0], vp[32]);
        }
    }
}

__device__ __forceinline__ uint32_t h2ex2(uint32_t x) {
    uint32_t r; asm("ex2.approx.f16x2 %0, %1;" : "=r"(r) : "r"(x)); return r;
}
__device__ __forceinline__ uint32_t smem_u32(const void* p) {
    uint32_t a;
    asm("{ .reg .u64 t; cvta.to.shared.u64 t, %1; cvt.u32.u64 %0, t; }" : "=r"(a) : "l"(p));
    return a;
}
__device__ __forceinline__ void cpasync16(uint32_t dst, const void* src) {
    asm volatile("cp.async.cg.shared.global [%0], [%1], 16;" :: "r"(dst), "l"(src));
}
#define CP_COMMIT() asm volatile("cp.async.commit_group;" ::: "memory")
#define CP_WAIT0()  asm volatile("cp.async.wait_group 0;" ::: "memory")

__device__ __forceinline__ void ldsm_x4(uint32_t& r0, uint32_t& r1, uint32_t& r2,
                                        uint32_t& r3, uint32_t addr) {
    asm volatile("ldmatrix.sync.aligned.m8n8.x4.shared.b16 {%0,%1,%2,%3}, [%4];"
                 : "=r"(r0), "=r"(r1), "=r"(r2), "=r"(r3) : "r"(addr));
}
__device__ __forceinline__ void mma16816(float c[4], const uint32_t a[4],
                                         uint32_t b0, uint32_t b1) {
    asm volatile(
        "mma.sync.aligned.m16n8k16.row.col.f32.f16.f16.f32 "
        "{%0,%1,%2,%3}, {%4,%5,%6,%7}, {%8,%9}, {%0,%1,%2,%3};\n"
        : "+f"(c[0]), "+f"(c[1]), "+f"(c[2]), "+f"(c[3])
        : "r"(a[0]), "r"(a[1]), "r"(a[2]), "r"(a[3]), "r"(b0), "r"(b1));
}

__global__ void __launch_bounds__(128, 4)
sdpa_fp16_kernel(const float* __restrict__ Q, float* __restrict__ O) {
    __shared__ __align__(16) char sbuf[2][TILE_BYTES];

    const int tid  = threadIdx.x;
    const int warp = tid >> 5;          // 0..3
    const int lane = tid & 31;
    const int g    = lane >> 2;
    const int t    = lane & 3;

    const int bh = blockIdx.y, b = bh / HEADS;
    const size_t base = (size_t)bh * S_LEN * 32;
    const int q_tile = blockIdx.x * BLOCK_M;
    const int q0 = q_tile + warp * 16 + g;           // rows q0, q0+8
    const uint32_t* mp0 = g_packed_mask + (size_t)b * S_LEN * MWORDS + (size_t)q0 * MWORDS;
    const uint32_t* mp1 = mp0 + 8 * MWORDS;

    const int lrow = lane & 7, lmat = lane >> 3;
    const uint32_t k_lane_off = (uint32_t)(lrow * K_ROW_B + 16 * lmat);
    const uint32_t v_lane_off = (uint32_t)(VT_OFF + lrow * VT_ROW_B + 16 * lmat);
    const uint32_t sb0 = smem_u32(&sbuf[0][0]);
    const uint32_t sb1 = smem_u32(&sbuf[1][0]);

    // hoisted cp.async addressing (128 threads -> 9 full chunks + partial)
    const uint32_t cpd0 = sb0 + tid * 16;
    const uint32_t cpd1 = sb1 + tid * 16;
    const char* cps = g_kvt + (size_t)bh * N_KTILES * TILE_BYTES + tid * 16;
    const bool cp9 = tid < (CHUNKS - 9 * 128);   // 1184 - 1152 = 32

    // ---- Q A-fragments (fp16, pre-scaled into log2 domain) ----
    uint32_t qa[2][4];
    #pragma unroll
    for (int kt = 0; kt < 2; kt++) {
        const int c0 = kt * 16 + 2 * t;
        float2 a0 = *reinterpret_cast<const float2*>(Q + base + (size_t)q0 * 32 + c0);
        float2 a1 = *reinterpret_cast<const float2*>(Q + base + (size_t)(q0 + 8) * 32 + c0);
        float2 a2 = *reinterpret_cast<const float2*>(Q + base + (size_t)q0 * 32 + c0 + 8);
        float2 a3 = *reinterpret_cast<const float2*>(Q + base + (size_t)(q0 + 8) * 32 + c0 + 8);
        qa[kt][0] = packh2(QSCALE * a0.x, QSCALE * a0.y);
        qa[kt][1] = packh2(QSCALE * a1.x, QSCALE * a1.y);
        qa[kt][2] = packh2(QSCALE * a2.x, QSCALE * a2.y);
        qa[kt][3] = packh2(QSCALE * a3.x, QSCALE * a3.y);
    }

    float o[4][4];
    #pragma unroll
    for (int i = 0; i < 4; i++)
        #pragma unroll
        for (int j = 0; j < 4; j++) o[i][j] = 0.f;
    float osum[4] = {0.f, 0.f, 0.f, 0.f};

    // ---- prologue: async-fill tile 0 into buffer 0 ----
    #pragma unroll
    for (int it = 0; it < 9; it++) cpasync16(cpd0 + it * 2048, cps + it * 2048);
    if (cp9) cpasync16(cpd0 + 9 * 2048, cps + 9 * 2048);
    CP_COMMIT();
    CP_WAIT0();
    __syncthreads();

    for (int kb = 0; kb < N_KTILES; kb++) {
        const int cur = kb & 1;
        const bool more = (kb + 1) < N_KTILES;
        const uint32_t sbc = cur ? sb1 : sb0;
        const uint32_t kbase = sbc + k_lane_off;
        const uint32_t vbase = sbc + v_lane_off;

        // ---- issue async fill of next tile into other buffer ----
        if (more) {
            const uint32_t cpd = cur ? cpd0 : cpd1;
            const char* src = cps + (size_t)(kb + 1) * TILE_BYTES;
            #pragma unroll
            for (int it = 0; it < 9; it++) cpasync16(cpd + it * 2048, src + it * 2048);
            if (cp9) cpasync16(cpd + 9 * 2048, src + 9 * 2048);
        }
        CP_COMMIT();

        // ---- mask words: 128 bits per row (uint4) ----
        uint4 mwa = *reinterpret_cast<const uint4*>(mp0 + kb * 4);
        uint4 mwb = *reinterpret_cast<const uint4*>(mp1 + kb * 4);
        const uint32_t w0[4] = {mwa.x, mwa.y, mwa.z, mwa.w};
        const uint32_t w1[4] = {mwb.x, mwb.y, mwb.z, mwb.w};

        uint32_t pfrag[16][2];

        // ==== two n64 halves: QK MMA -> select-mask -> pack -> ex2 ====
        #pragma unroll
        for (int h = 0; h < 2; h++) {
            float s[8][4];
            #pragma unroll
            for (int nt = 0; nt < 8; nt++)
                #pragma unroll
                for (int j = 0; j < 4; j++) s[nt][j] = 0.f;

            const uint32_t kh = kbase + h * (64 * K_ROW_B);
            #pragma unroll
            for (int nt = 0; nt < 8; nt++) {
                uint32_t b0, b1, b2, b3;
                ldsm_x4(b0, b1, b2, b3, kh + nt * (8 * K_ROW_B));
                mma16816(s[nt], qa[0], b0, b1);
                mma16816(s[nt], qa[1], b2, b3);
            }

            #pragma unroll
            for (int nt = 0; nt < 8; nt++) {
                const int wi = 2 * h + (nt >> 2);
                const int sh = (nt & 3) * 8 + 2 * t;
                uint32_t b0 = w0[wi] >> sh;
                uint32_t b1 = w1[wi] >> sh;
                float s0 = (b0 & 1u) ? -1e9f : s[nt][0];
                float s1 = (b0 & 2u) ? -1e9f : s[nt][1];
                float s2 = (b1 & 1u) ? -1e9f : s[nt][2];
                float s3 = (b1 & 2u) ? -1e9f : s[nt][3];
                pfrag[8 * h + nt][0] = h2ex2(packh2(s0, s1));
                pfrag[8 * h + nt][1] = h2ex2(packh2(s2, s3));
            }
        }

        // ---- O += P V : per d-block, 8 k16 key-blocks ----
        #pragma unroll
        for (int nt2 = 0; nt2 < 4; nt2++) {
            uint32_t vb[16];
            const uint32_t va = vbase + nt2 * (8 * VT_ROW_B);
            #pragma unroll
            for (int c = 0; c < 4; c++)
                ldsm_x4(vb[4 * c], vb[4 * c + 1], vb[4 * c + 2], vb[4 * c + 3],
                        va + 64 * c);
            #pragma unroll
            for (int kt = 0; kt < 8; kt++) {
                uint32_t pa[4] = {pfrag[2 * kt][0], pfrag[2 * kt][1],
                                  pfrag[2 * kt + 1][0], pfrag[2 * kt + 1][1]};
                mma16816(o[nt2], pa, vb[2 * kt], vb[2 * kt + 1]);
            }
        }
        // ---- row sums via constant-ones B ----
        #pragma unroll
        for (int kt = 0; kt < 8; kt++) {
            uint32_t pa[4] = {pfrag[2 * kt][0], pfrag[2 * kt][1],
                              pfrag[2 * kt + 1][0], pfrag[2 * kt + 1][1]};
            mma16816(osum, pa, ONE_H2, ONE_H2);
        }

        CP_WAIT0();
        __syncthreads();
    }

    // ---- epilogue ----
    const float inv0 = 1.f / osum[0];   // row q0
    const float inv1 = 1.f / osum[2];   // row q0+8
    #pragma unroll
    for (int nt2 = 0; nt2 < 4; nt2++) {
        const int c = nt2 * 8 + 2 * t;
        float2 va = make_float2(o[nt2][0] * inv0, o[nt2][1] * inv0);
        float2 vb = make_float2(o[nt2][2] * inv1, o[nt2][3] * inv1);
        *reinterpret_cast<float2*>(O + base + (size_t)q0 * 32 + c) = va;
        *reinterpret_cast<float2*>(O + base + (size_t)(q0 + 8) * 32 + c) = vb;
    }
}

extern "C" void kernel_launch(void* const* d_in, const int* in_sizes, int n_in,
                              void* d_out, int out_size) {
    const float* Q = (const float*)d_in[0];
    const float* K = (const float*)d_in[1];
    const float* V = (const float*)d_in[2];
    const int4* mask = (const int4*)d_in[3];
    float* O = (float*)d_out;

    prep_all_kernel<<<MASK_BLOCKS + PREP_BLOCKS, 256>>>(mask, K, V);
    dim3 grid(S_LEN / BLOCK_M, 48);   // (32, 48)
    sdpa_fp16_kernel<<<grid, 128>>>(Q, O);
}